// round 1
// baseline (speedup 1.0000x reference)
#include <cuda_runtime.h>

// ---------------------------------------------------------------------------
// ChunkedCrossAttention  (B=4, S=2048, D=1024, C=32, N=2, L=128, H=16, DK=64)
//
// Pipeline (6 launches, all default stream, graph-capturable):
//   1. ln_kernel      : LayerNorm(h[:,63:]) -> g_hsn (zero-padded to 2048 rows/batch)
//   2. sgemm<false>   : g_q  = g_hsn @ Wq + bq          (8192 x 1024 x 1024)
//   3. sgemm<false>   : g_k  = e     @ Wk + bk          (32768 x 1024 x 1024)
//   4. sgemm<false>   : g_v  = e     @ Wv + bv          (32768 x 1024 x 1024)
//   5. attn_kernel    : per (b,c,h): softmax(QK^T/8) V -> g_ao
//   6. sgemm<true>    : out  = h + shift63(g_ao @ Wo + bo)   (fused epilogue)
// ---------------------------------------------------------------------------

#define VALID_ROWS 1985   // S - CHUNK + 1

// ---------------- scratch (device globals; no allocation allowed) ----------
__device__ float g_hsn[4 * 2048 * 1024];        // normalized/padded queries input
__device__ float g_q  [4 * 2048 * 1024];        // Q  (B, 2048, 1024)
__device__ float g_k  [4 * 32 * 256 * 1024];    // K  (B, C, 256, H*DK)
__device__ float g_v  [4 * 32 * 256 * 1024];    // V  (B, C, 256, H*DK)
__device__ float g_ao [4 * 2048 * 1024];        // attention output (B, 2048, 1024)

// ---------------------------------------------------------------------------
// 1. LayerNorm: row m = (b, t); t < 1985 -> LN(h[b, t+63]); else zeros.
// 256 threads, one float4 per thread (D = 1024).
// ---------------------------------------------------------------------------
__global__ void ln_kernel(const float* __restrict__ h,
                          const float* __restrict__ gamma,
                          const float* __restrict__ beta) {
    const int m = blockIdx.x;           // 0 .. 8191
    const int b = m >> 11;
    const int t = m & 2047;
    const int tid = threadIdx.x;

    float4* dst = reinterpret_cast<float4*>(g_hsn + (long)m * 1024) + tid;
    if (t >= VALID_ROWS) {              // uniform across block
        *dst = make_float4(0.f, 0.f, 0.f, 0.f);
        return;
    }
    const float4* src =
        reinterpret_cast<const float4*>(h + ((long)(b * 2048 + t + 63)) * 1024) + tid;
    float4 x = *src;

    float s = x.x + x.y + x.z + x.w;
    float q = x.x * x.x + x.y * x.y + x.z * x.z + x.w * x.w;
    #pragma unroll
    for (int o = 16; o > 0; o >>= 1) {
        s += __shfl_xor_sync(0xFFFFFFFFu, s, o);
        q += __shfl_xor_sync(0xFFFFFFFFu, q, o);
    }
    __shared__ float rs[8], rq[8];
    const int w = tid >> 5;
    if ((tid & 31) == 0) { rs[w] = s; rq[w] = q; }
    __syncthreads();
    s = 0.f; q = 0.f;
    #pragma unroll
    for (int i = 0; i < 8; i++) { s += rs[i]; q += rq[i]; }

    const float mu   = s * (1.0f / 1024.0f);
    const float var  = q * (1.0f / 1024.0f) - mu * mu;
    const float rstd = rsqrtf(var + 1e-5f);

    float4 g  = reinterpret_cast<const float4*>(gamma)[tid];
    float4 bb = reinterpret_cast<const float4*>(beta )[tid];
    float4 o;
    o.x = (x.x - mu) * rstd * g.x + bb.x;
    o.y = (x.y - mu) * rstd * g.y + bb.y;
    o.z = (x.z - mu) * rstd * g.z + bb.z;
    o.w = (x.w - mu) * rstd * g.w + bb.w;
    *dst = o;
}

// ---------------------------------------------------------------------------
// 2-4, 6. SGEMM  C[M,1024] = A[M,1024] @ W[1024,1024] + bias
//   BM=BN=128, BK=16, 256 threads, 8x8 per thread, smem double-buffered.
//   SHIFT variant (O-projection): A row for output row (b,t) is
//   g_ao[b*2048 + t - 63] when t>=63 else a zero row; epilogue adds residual
//   h[b,t] and bias (bias only for t>=63), writing the final output.
// ---------------------------------------------------------------------------
template <bool SHIFT>
__global__ void sgemm_k(const float* __restrict__ A, const float* __restrict__ W,
                        const float* __restrict__ bias, const float* __restrict__ resid,
                        float* __restrict__ Cm) {
    __shared__ float As[2][16][132];
    __shared__ float Bs[2][16][132];

    const int n0  = blockIdx.x * 128;
    const int m0  = blockIdx.y * 128;
    const int tid = threadIdx.x;
    const int tm  = (tid >> 4) << 3;     // 0..120
    const int tn  = (tid & 15) << 3;     // 0..120

    // loader coordinates
    const int ar0 = tid >> 2, ar1 = ar0 + 64;  // A tile rows
    const int ac  = (tid & 3) * 4;             // A tile k-cols (4 of 16)
    const int br0 = tid >> 5, br1 = br0 + 8;   // B tile k-rows
    const int bc  = (tid & 31) * 4;            // B tile n-cols

    const int gm0 = m0 + ar0, gm1 = m0 + ar1;
    bool av0 = true, av1 = true;
    const float *ap0, *ap1;
    if (SHIFT) {
        av0 = (gm0 & 2047) >= 63;
        av1 = (gm1 & 2047) >= 63;
        ap0 = A + (long)(gm0 - 63) * 1024 + ac;
        ap1 = A + (long)(gm1 - 63) * 1024 + ac;
    } else {
        ap0 = A + (long)gm0 * 1024 + ac;
        ap1 = A + (long)gm1 * 1024 + ac;
    }
    const float* bp0 = W + (long)br0 * 1024 + n0 + bc;
    const float* bp1 = W + (long)br1 * 1024 + n0 + bc;

    float acc[8][8];
    #pragma unroll
    for (int i = 0; i < 8; i++)
        #pragma unroll
        for (int j = 0; j < 8; j++) acc[i][j] = 0.f;

    const float4 fz = make_float4(0.f, 0.f, 0.f, 0.f);
    float4 pa0, pa1, pb0, pb1;

    // prologue: fetch tile 0 and store to buffer 0
    pa0 = av0 ? *reinterpret_cast<const float4*>(ap0) : fz;
    pa1 = av1 ? *reinterpret_cast<const float4*>(ap1) : fz;
    pb0 = *reinterpret_cast<const float4*>(bp0);
    pb1 = *reinterpret_cast<const float4*>(bp1);
    As[0][ac + 0][ar0] = pa0.x; As[0][ac + 1][ar0] = pa0.y;
    As[0][ac + 2][ar0] = pa0.z; As[0][ac + 3][ar0] = pa0.w;
    As[0][ac + 0][ar1] = pa1.x; As[0][ac + 1][ar1] = pa1.y;
    As[0][ac + 2][ar1] = pa1.z; As[0][ac + 3][ar1] = pa1.w;
    *reinterpret_cast<float4*>(&Bs[0][br0][bc]) = pb0;
    *reinterpret_cast<float4*>(&Bs[0][br1][bc]) = pb1;
    __syncthreads();

    int buf = 0;
    for (int kt = 0; kt < 64; kt++) {
        if (kt < 63) {  // prefetch next tile into registers
            const int k0 = (kt + 1) * 16;
            pa0 = av0 ? *reinterpret_cast<const float4*>(ap0 + k0) : fz;
            pa1 = av1 ? *reinterpret_cast<const float4*>(ap1 + k0) : fz;
            pb0 = *reinterpret_cast<const float4*>(bp0 + (long)k0 * 1024);
            pb1 = *reinterpret_cast<const float4*>(bp1 + (long)k0 * 1024);
        }
        #pragma unroll
        for (int kk = 0; kk < 16; kk++) {
            float4 a0 = *reinterpret_cast<const float4*>(&As[buf][kk][tm]);
            float4 a1 = *reinterpret_cast<const float4*>(&As[buf][kk][tm + 4]);
            float4 b0 = *reinterpret_cast<const float4*>(&Bs[buf][kk][tn]);
            float4 b1 = *reinterpret_cast<const float4*>(&Bs[buf][kk][tn + 4]);
            float a_[8] = {a0.x, a0.y, a0.z, a0.w, a1.x, a1.y, a1.z, a1.w};
            float b_[8] = {b0.x, b0.y, b0.z, b0.w, b1.x, b1.y, b1.z, b1.w};
            #pragma unroll
            for (int i = 0; i < 8; i++)
                #pragma unroll
                for (int j = 0; j < 8; j++)
                    acc[i][j] += a_[i] * b_[j];
        }
        if (kt < 63) {
            const int nb = buf ^ 1;
            As[nb][ac + 0][ar0] = pa0.x; As[nb][ac + 1][ar0] = pa0.y;
            As[nb][ac + 2][ar0] = pa0.z; As[nb][ac + 3][ar0] = pa0.w;
            As[nb][ac + 0][ar1] = pa1.x; As[nb][ac + 1][ar1] = pa1.y;
            As[nb][ac + 2][ar1] = pa1.z; As[nb][ac + 3][ar1] = pa1.w;
            *reinterpret_cast<float4*>(&Bs[nb][br0][bc]) = pb0;
            *reinterpret_cast<float4*>(&Bs[nb][br1][bc]) = pb1;
            __syncthreads();
            buf = nb;
        }
    }

    // epilogue
    float bs_[8];
    #pragma unroll
    for (int j = 0; j < 8; j++) bs_[j] = bias[n0 + tn + j];

    #pragma unroll
    for (int i = 0; i < 8; i++) {
        const int m = m0 + tm + i;
        float* cp = Cm + (long)m * 1024 + n0 + tn;
        if (SHIFT) {
            const float* rp = resid + (long)m * 1024 + n0 + tn;
            float4 r0 = *reinterpret_cast<const float4*>(rp);
            float4 r1 = *reinterpret_cast<const float4*>(rp + 4);
            float4 o0, o1;
            if ((m & 2047) >= 63) {
                o0 = make_float4(r0.x + acc[i][0] + bs_[0], r0.y + acc[i][1] + bs_[1],
                                 r0.z + acc[i][2] + bs_[2], r0.w + acc[i][3] + bs_[3]);
                o1 = make_float4(r1.x + acc[i][4] + bs_[4], r1.y + acc[i][5] + bs_[5],
                                 r1.z + acc[i][6] + bs_[6], r1.w + acc[i][7] + bs_[7]);
            } else {
                o0 = r0; o1 = r1;   // rows t<63: output = residual only
            }
            *reinterpret_cast<float4*>(cp)     = o0;
            *reinterpret_cast<float4*>(cp + 4) = o1;
        } else {
            float4 o0 = make_float4(acc[i][0] + bs_[0], acc[i][1] + bs_[1],
                                    acc[i][2] + bs_[2], acc[i][3] + bs_[3]);
            float4 o1 = make_float4(acc[i][4] + bs_[4], acc[i][5] + bs_[5],
                                    acc[i][6] + bs_[6], acc[i][7] + bs_[7]);
            *reinterpret_cast<float4*>(cp)     = o0;
            *reinterpret_cast<float4*>(cp + 4) = o1;
        }
    }
}

// ---------------------------------------------------------------------------
// 5. Attention: one block per (b, c, h). 256 threads.
//    scores S = Q(64x64) K^T(64x256) * SCALE   -> ss[qi][j]  (row softmax)
//    out    O = P(64x256) V(256x64)            -> g_ao
// smem: qT [64][68] (q transposed, d-major), ss [64][260],
//       kv union { ksT [64][260] ; vs [256][68] }, rsum [64]
// ---------------------------------------------------------------------------
#define ATT_SMEM_FLOATS (4352 + 16640 + 17408 + 64)
#define ATT_SMEM_BYTES  (ATT_SMEM_FLOATS * 4)

__global__ void attn_kernel() {
    extern __shared__ float sm[];
    float* qT   = sm;                    // [d*68 + qi]
    float* ss   = sm + 4352;             // [qi*260 + j]
    float* kv   = sm + 4352 + 16640;     // ksT: [d*260 + j]  /  vs: [j*68 + d]
    float* rsum = sm + 4352 + 16640 + 17408;

    const int tid = threadIdx.x;
    const int hh = blockIdx.x, c = blockIdx.y, b = blockIdx.z;

    const float* qg = g_q + (long)(b * 2048 + c * 64) * 1024 + hh * 64;
    const long  kvbase = ((long)(b * 32 + c) * 256) * 1024 + hh * 64;
    const float* kg = g_k + kvbase;
    const float* vg = g_v + kvbase;

    // ---- load Q transposed: qT[d][qi] ----
    #pragma unroll
    for (int rep = 0; rep < 4; rep++) {
        const int f  = tid + 256 * rep;
        const int qi = f >> 4;
        const int d4 = (f & 15) * 4;
        float4 v = *reinterpret_cast<const float4*>(qg + (long)qi * 1024 + d4);
        qT[(d4 + 0) * 68 + qi] = v.x;
        qT[(d4 + 1) * 68 + qi] = v.y;
        qT[(d4 + 2) * 68 + qi] = v.z;
        qT[(d4 + 3) * 68 + qi] = v.w;
    }
    // ---- load K transposed: ksT[d][j]  (j = tid -> conflict-free smem) ----
    #pragma unroll
    for (int rep = 0; rep < 16; rep++) {
        const int d4 = rep * 4;
        float4 v = *reinterpret_cast<const float4*>(kg + (long)tid * 1024 + d4);
        kv[(d4 + 0) * 260 + tid] = v.x;
        kv[(d4 + 1) * 260 + tid] = v.y;
        kv[(d4 + 2) * 260 + tid] = v.z;
        kv[(d4 + 3) * 260 + tid] = v.w;
    }
    __syncthreads();

    // ---- scores GEMM: 8x8 per thread over (qi, j) ----
    {
        const int tm = (tid >> 5) << 3;   // qi base (warp-uniform)
        const int tn = (tid & 31) << 3;   // j  base
        float s[8][8];
        #pragma unroll
        for (int i = 0; i < 8; i++)
            #pragma unroll
            for (int j = 0; j < 8; j++) s[i][j] = 0.f;

        #pragma unroll 4
        for (int d = 0; d < 64; d++) {
            float4 a0 = *reinterpret_cast<const float4*>(&qT[d * 68 + tm]);
            float4 a1 = *reinterpret_cast<const float4*>(&qT[d * 68 + tm + 4]);
            float4 b0 = *reinterpret_cast<const float4*>(&kv[d * 260 + tn]);
            float4 b1 = *reinterpret_cast<const float4*>(&kv[d * 260 + tn + 4]);
            float a_[8] = {a0.x, a0.y, a0.z, a0.w, a1.x, a1.y, a1.z, a1.w};
            float b_[8] = {b0.x, b0.y, b0.z, b0.w, b1.x, b1.y, b1.z, b1.w};
            #pragma unroll
            for (int i = 0; i < 8; i++)
                #pragma unroll
                for (int j = 0; j < 8; j++)
                    s[i][j] += a_[i] * b_[j];
        }
        const float SC = 0.125f;   // 1/sqrt(64)
        #pragma unroll
        for (int i = 0; i < 8; i++) {
            float4 s0 = make_float4(s[i][0] * SC, s[i][1] * SC, s[i][2] * SC, s[i][3] * SC);
            float4 s1 = make_float4(s[i][4] * SC, s[i][5] * SC, s[i][6] * SC, s[i][7] * SC);
            *reinterpret_cast<float4*>(&ss[(tm + i) * 260 + tn])     = s0;
            *reinterpret_cast<float4*>(&ss[(tm + i) * 260 + tn + 4]) = s1;
        }
    }
    __syncthreads();

    // ---- load V (overwrites ksT region) — overlapped with softmax ----
    #pragma unroll
    for (int rep = 0; rep < 16; rep++) {
        const int f  = tid + 256 * rep;
        const int j  = f >> 4;
        const int d4 = (f & 15) * 4;
        float4 v = *reinterpret_cast<const float4*>(vg + (long)j * 1024 + d4);
        *reinterpret_cast<float4*>(&kv[j * 68 + d4]) = v;
    }
    // ---- softmax per row (threads 0..63) ----
    if (tid < 64) {
        float* row = ss + tid * 260;
        float mx = -1e30f;
        #pragma unroll 8
        for (int j = 0; j < 256; j++) mx = fmaxf(mx, row[j]);
        float sum = 0.f;
        #pragma unroll 8
        for (int j = 0; j < 256; j++) {
            float e_ = __expf(row[j] - mx);
            row[j] = e_;
            sum += e_;
        }
        rsum[tid] = 1.0f / sum;
    }
    __syncthreads();

    // ---- output GEMM: 4x4 per thread over (qi, d), K-dim = 256 keys ----
    {
        const int tm2 = (tid >> 4) << 2;   // qi base
        const int tn2 = (tid & 15) << 2;   // d  base
        float o[4][4];
        #pragma unroll
        for (int i = 0; i < 4; i++)
            #pragma unroll
            for (int j = 0; j < 4; j++) o[i][j] = 0.f;

        #pragma unroll 4
        for (int j = 0; j < 256; j++) {
            float4 bv = *reinterpret_cast<const float4*>(&kv[j * 68 + tn2]);
            #pragma unroll
            for (int i = 0; i < 4; i++) {
                float a = ss[(tm2 + i) * 260 + j];
                o[i][0] += a * bv.x;
                o[i][1] += a * bv.y;
                o[i][2] += a * bv.z;
                o[i][3] += a * bv.w;
            }
        }
        float* og = g_ao + (long)(b * 2048 + c * 64) * 1024 + hh * 64;
        #pragma unroll
        for (int i = 0; i < 4; i++) {
            const float r = rsum[tm2 + i];
            float4 w = make_float4(o[i][0] * r, o[i][1] * r, o[i][2] * r, o[i][3] * r);
            *reinterpret_cast<float4*>(og + (long)(tm2 + i) * 1024 + tn2) = w;
        }
    }
}

// ---------------------------------------------------------------------------
extern "C" void kernel_launch(void* const* d_in, const int* in_sizes, int n_in,
                              void* d_out, int out_size) {
    (void)in_sizes; (void)n_in; (void)out_size;
    const float* h     = (const float*)d_in[0];
    const float* e     = (const float*)d_in[1];
    const float* Wq    = (const float*)d_in[2];
    const float* bq    = (const float*)d_in[3];
    const float* Wk    = (const float*)d_in[4];
    const float* bk    = (const float*)d_in[5];
    const float* Wv    = (const float*)d_in[6];
    const float* bv    = (const float*)d_in[7];
    const float* Wo    = (const float*)d_in[8];
    const float* bo    = (const float*)d_in[9];
    const float* gamma = (const float*)d_in[10];
    const float* beta  = (const float*)d_in[11];
    float* out = (float*)d_out;

    void *p_hsn, *p_q, *p_k, *p_v, *p_ao;
    cudaGetSymbolAddress(&p_hsn, g_hsn);
    cudaGetSymbolAddress(&p_q,   g_q);
    cudaGetSymbolAddress(&p_k,   g_k);
    cudaGetSymbolAddress(&p_v,   g_v);
    cudaGetSymbolAddress(&p_ao,  g_ao);

    cudaFuncSetAttribute(attn_kernel, cudaFuncAttributeMaxDynamicSharedMemorySize,
                         ATT_SMEM_BYTES);

    // 1. LayerNorm + pad
    ln_kernel<<<4 * 2048, 256>>>(h, gamma, beta);
    // 2. Q projection
    sgemm_k<false><<<dim3(8, 64),  256>>>((const float*)p_hsn, Wq, bq, nullptr, (float*)p_q);
    // 3. K projection
    sgemm_k<false><<<dim3(8, 256), 256>>>(e, Wk, bk, nullptr, (float*)p_k);
    // 4. V projection
    sgemm_k<false><<<dim3(8, 256), 256>>>(e, Wv, bv, nullptr, (float*)p_v);
    // 5. Attention
    attn_kernel<<<dim3(16, 32, 4), 256, ATT_SMEM_BYTES>>>();
    // 6. Output projection + shift + bias + residual
    sgemm_k<true><<<dim3(8, 64), 256>>>((const float*)p_ao, Wo, bo, h, out);
}

// round 3
// speedup vs baseline: 1.9264x; 1.9264x over previous
#include <cuda_runtime.h>
#include <cstdint>

// ---------------------------------------------------------------------------
// ChunkedCrossAttention  (B=4, S=2048, D=1024, C=32, N=2, L=128, H=16, DK=64)
// Round 2: projection GEMMs on mma.sync tf32 (legacy tensor path, valid on
// plain compute_100 PTX — tcgen05 is sm_100a-only and the harness compiles
// via compute_100, so mma.sync is the fastest reachable tensor path).
//
// Launches:
//   1. ln_kernel          LayerNorm(h[:,63:]) -> g_hsn (padded)
//   2. transpose_w x4     W[k][n] -> WT[n][k]  (+ round-to-tf32)
//   3. mma_gemm<false>    g_q = g_hsn @ Wq + bq
//   4. mma_gemm<false>    g_k = e @ Wk + bk
//   5. mma_gemm<false>    g_v = e @ Wv + bv
//   6. attn_kernel        per (b,c,h): softmax(QK^T/8) V -> g_ao
//   7. mma_gemm<true>     out = h + shift63(g_ao @ Wo + bo)
// ---------------------------------------------------------------------------

#define VALID_ROWS 1985

// ---------------- scratch ----------------
__device__ float g_hsn[4 * 2048 * 1024];
__device__ float g_q  [4 * 2048 * 1024];
__device__ float g_k  [4 * 32 * 256 * 1024];
__device__ float g_v  [4 * 32 * 256 * 1024];
__device__ float g_ao [4 * 2048 * 1024];
__device__ float g_wT [4 * 1024 * 1024];     // transposed, tf32-rounded weights

// ---------------- helpers ----------------
__device__ __forceinline__ float f2tf(float x) {
    uint32_t u;
    asm("cvt.rn.tf32.f32 %0, %1;" : "=r"(u) : "f"(x));
    return __uint_as_float(u);
}
__device__ __forceinline__ uint32_t f2tf_u(float x) {
    uint32_t u;
    asm("cvt.rn.tf32.f32 %0, %1;" : "=r"(u) : "f"(x));
    return u;
}
__device__ __forceinline__ uint32_t smem_u32(const void* p) {
    uint32_t a;
    asm("{ .reg .u64 t; cvta.to.shared.u64 t, %1; cvt.u32.u64 %0, t; }" : "=r"(a) : "l"(p));
    return a;
}
#define CP_ASYNC16(dst, src) \
    asm volatile("cp.async.cg.shared.global [%0], [%1], 16;" :: "r"(dst), "l"(src) : "memory")
#define CP_COMMIT() asm volatile("cp.async.commit_group;" ::: "memory")
#define CP_WAIT(n)  asm volatile("cp.async.wait_group %0;" :: "n"(n) : "memory")

#define MMA_TF32(c, a, b) \
    asm volatile("mma.sync.aligned.m16n8k8.row.col.f32.tf32.tf32.f32 " \
                 "{%0,%1,%2,%3}, {%4,%5,%6,%7}, {%8,%9}, {%0,%1,%2,%3};" \
                 : "+f"((c)[0]), "+f"((c)[1]), "+f"((c)[2]), "+f"((c)[3]) \
                 : "r"((a)[0]), "r"((a)[1]), "r"((a)[2]), "r"((a)[3]), \
                   "r"((b)[0]), "r"((b)[1]))

// ---------------------------------------------------------------------------
// 1. LayerNorm
// ---------------------------------------------------------------------------
__global__ void ln_kernel(const float* __restrict__ h,
                          const float* __restrict__ gamma,
                          const float* __restrict__ beta) {
    const int m = blockIdx.x;
    const int b = m >> 11;
    const int t = m & 2047;
    const int tid = threadIdx.x;

    float4* dst = reinterpret_cast<float4*>(g_hsn + (long)m * 1024) + tid;
    if (t >= VALID_ROWS) { *dst = make_float4(0.f, 0.f, 0.f, 0.f); return; }
    const float4* src =
        reinterpret_cast<const float4*>(h + ((long)(b * 2048 + t + 63)) * 1024) + tid;
    float4 x = *src;

    float s = x.x + x.y + x.z + x.w;
    float q = x.x * x.x + x.y * x.y + x.z * x.z + x.w * x.w;
    #pragma unroll
    for (int o = 16; o > 0; o >>= 1) {
        s += __shfl_xor_sync(0xFFFFFFFFu, s, o);
        q += __shfl_xor_sync(0xFFFFFFFFu, q, o);
    }
    __shared__ float rs[8], rq[8];
    const int w = tid >> 5;
    if ((tid & 31) == 0) { rs[w] = s; rq[w] = q; }
    __syncthreads();
    s = 0.f; q = 0.f;
    #pragma unroll
    for (int i = 0; i < 8; i++) { s += rs[i]; q += rq[i]; }

    const float mu   = s * (1.0f / 1024.0f);
    const float var  = q * (1.0f / 1024.0f) - mu * mu;
    const float rstd = rsqrtf(var + 1e-5f);

    float4 g  = reinterpret_cast<const float4*>(gamma)[tid];
    float4 bb = reinterpret_cast<const float4*>(beta )[tid];
    float4 o;
    o.x = (x.x - mu) * rstd * g.x + bb.x;
    o.y = (x.y - mu) * rstd * g.y + bb.y;
    o.z = (x.z - mu) * rstd * g.z + bb.z;
    o.w = (x.w - mu) * rstd * g.w + bb.w;
    *dst = o;
}

// ---------------------------------------------------------------------------
// 2. Transpose + tf32-round: WT[n][k] = rn_tf32(W[k][n]), 1024x1024
// ---------------------------------------------------------------------------
__global__ void transpose_w(const float* __restrict__ src, float* __restrict__ dst) {
    __shared__ float t[32][33];
    const int x  = blockIdx.x * 32 + threadIdx.x;
    const int y0 = blockIdx.y * 32 + threadIdx.y;
    #pragma unroll
    for (int i = 0; i < 4; i++)
        t[threadIdx.y + 8 * i][threadIdx.x] = src[(long)(y0 + 8 * i) * 1024 + x];
    __syncthreads();
    const int x2  = blockIdx.y * 32 + threadIdx.x;
    const int y20 = blockIdx.x * 32 + threadIdx.y;
    #pragma unroll
    for (int i = 0; i < 4; i++)
        dst[(long)(y20 + 8 * i) * 1024 + x2] = f2tf(t[threadIdx.x][threadIdx.y + 8 * i]);
}

// ---------------------------------------------------------------------------
// 3. mma.sync tf32 GEMM:  C[M,1024] = A[M,1024] @ WT^T + bias
//    BM=BN=128, BK=32, 256 thr, warp tile 32x64, cp.async 2-stage.
//    SHIFT: A row for output row m is A[m-63] (zero if (m&2047)<63);
//           epilogue adds resid; bias only on valid rows.
// ---------------------------------------------------------------------------
#define PAD 36
#define TILE_F (128 * PAD)                 // floats per tile buffer
#define GM_SMEM (4 * TILE_F * 4)           // A[2] + B[2] = 73728 bytes

template <bool SHIFT>
__global__ void __launch_bounds__(256)
mma_gemm(const float* __restrict__ A, const float* __restrict__ WT,
         const float* __restrict__ bias, const float* __restrict__ resid,
         float* __restrict__ Cm) {
    extern __shared__ float smem[];
    float* Asm = smem;                 // [2][128][PAD]
    float* Bsm = smem + 2 * TILE_F;    // [2][128][PAD]

    const int tid  = threadIdx.x;
    const int wid  = tid >> 5;
    const int lane = tid & 31;
    const int g    = lane >> 2;        // 0..7
    const int tig  = lane & 3;         // 0..3

    const int n0 = blockIdx.x * 128;
    const int m0 = blockIdx.y * 128;
    const int warp_m = (wid & 3) * 32;
    const int warp_n = (wid >> 2) * 64;

    // ---- loader coordinates: thread t -> row t>>1, col (t&1)*16, 4x float4
    const int lrow = tid >> 1;
    const int lcol = (tid & 1) * 16;
    const int am   = m0 + lrow;
    bool avalid = true;
    const float* aptr;
    if (SHIFT) {
        avalid = (am & 2047) >= 63;
        aptr = avalid ? (A + (long)(am - 63) * 1024 + lcol) : A;
    } else {
        aptr = A + (long)am * 1024 + lcol;
    }
    const float* bptr = WT + (long)(n0 + lrow) * 1024 + lcol;

    const uint32_t a_s = smem_u32(Asm) + (uint32_t)(lrow * PAD + lcol) * 4;
    const uint32_t b_s = smem_u32(Bsm) + (uint32_t)(lrow * PAD + lcol) * 4;

    auto load_tile = [&](int kt, int s) {
        const uint32_t ad = a_s + (uint32_t)s * TILE_F * 4;
        const uint32_t bd = b_s + (uint32_t)s * TILE_F * 4;
        const float* ap = aptr + kt * 32;
        const float* bp = bptr + kt * 32;
        if (avalid) {
            #pragma unroll
            for (int i = 0; i < 4; i++) CP_ASYNC16(ad + i * 16, ap + i * 4);
        } else {
            #pragma unroll
            for (int i = 0; i < 4; i++)
                *reinterpret_cast<float4*>(
                    &Asm[s * TILE_F + lrow * PAD + lcol + i * 4]) =
                    make_float4(0.f, 0.f, 0.f, 0.f);
        }
        #pragma unroll
        for (int i = 0; i < 4; i++) CP_ASYNC16(bd + i * 16, bp + i * 4);
    };

    float c[2][8][4];
    #pragma unroll
    for (int mi = 0; mi < 2; mi++)
        #pragma unroll
        for (int ni = 0; ni < 8; ni++)
            #pragma unroll
            for (int r = 0; r < 4; r++) c[mi][ni][r] = 0.f;

    load_tile(0, 0);
    CP_COMMIT();

    #pragma unroll 1
    for (int kt = 0; kt < 32; kt++) {
        const int s = kt & 1;
        if (kt + 1 < 32) {
            load_tile(kt + 1, s ^ 1);
            CP_COMMIT();
            CP_WAIT(1);
        } else {
            CP_WAIT(0);
        }
        __syncthreads();

        const float* As = Asm + s * TILE_F;
        const float* Bs = Bsm + s * TILE_F;
        #pragma unroll
        for (int ks = 0; ks < 4; ks++) {
            uint32_t a[2][4];
            #pragma unroll
            for (int mi = 0; mi < 2; mi++) {
                const float* ab = As + (warp_m + mi * 16 + g) * PAD + ks * 8 + tig;
                a[mi][0] = f2tf_u(ab[0]);
                a[mi][1] = f2tf_u(ab[8 * PAD]);
                a[mi][2] = f2tf_u(ab[4]);
                a[mi][3] = f2tf_u(ab[8 * PAD + 4]);
            }
            uint32_t b[8][2];
            #pragma unroll
            for (int ni = 0; ni < 8; ni++) {
                const float* bb = Bs + (warp_n + ni * 8 + g) * PAD + ks * 8 + tig;
                b[ni][0] = __float_as_uint(bb[0]);   // WT pre-rounded
                b[ni][1] = __float_as_uint(bb[4]);
            }
            #pragma unroll
            for (int mi = 0; mi < 2; mi++)
                #pragma unroll
                for (int ni = 0; ni < 8; ni++)
                    MMA_TF32(c[mi][ni], a[mi], b[ni]);
        }
        __syncthreads();
    }

    // ---- epilogue ----
    #pragma unroll
    for (int mi = 0; mi < 2; mi++) {
        const int r0 = m0 + warp_m + mi * 16 + g;
        const int r1 = r0 + 8;
        #pragma unroll
        for (int ni = 0; ni < 8; ni++) {
            const int col = n0 + warp_n + ni * 8 + 2 * tig;
            float2 bs = *reinterpret_cast<const float2*>(bias + col);
            float2 o0 = make_float2(c[mi][ni][0], c[mi][ni][1]);
            float2 o1 = make_float2(c[mi][ni][2], c[mi][ni][3]);
            if (SHIFT) {
                float2 rv0 = *reinterpret_cast<const float2*>(resid + (long)r0 * 1024 + col);
                float2 rv1 = *reinterpret_cast<const float2*>(resid + (long)r1 * 1024 + col);
                if ((r0 & 2047) >= 63) {
                    o0.x += bs.x + rv0.x; o0.y += bs.y + rv0.y;
                } else o0 = rv0;
                if ((r1 & 2047) >= 63) {
                    o1.x += bs.x + rv1.x; o1.y += bs.y + rv1.y;
                } else o1 = rv1;
            } else {
                o0.x += bs.x; o0.y += bs.y;
                o1.x += bs.x; o1.y += bs.y;
            }
            *reinterpret_cast<float2*>(Cm + (long)r0 * 1024 + col) = o0;
            *reinterpret_cast<float2*>(Cm + (long)r1 * 1024 + col) = o1;
        }
    }
}

// ---------------------------------------------------------------------------
// 5. Attention: one block per (b, c, h), 256 threads (unchanged).
// ---------------------------------------------------------------------------
#define ATT_SMEM_FLOATS (4352 + 16640 + 17408 + 64)
#define ATT_SMEM_BYTES  (ATT_SMEM_FLOATS * 4)

__global__ void attn_kernel() {
    extern __shared__ float sm[];
    float* qT   = sm;
    float* ss   = sm + 4352;
    float* kv   = sm + 4352 + 16640;
    float* rsum = sm + 4352 + 16640 + 17408;

    const int tid = threadIdx.x;
    const int hh = blockIdx.x, c = blockIdx.y, b = blockIdx.z;

    const float* qg = g_q + (long)(b * 2048 + c * 64) * 1024 + hh * 64;
    const long  kvbase = ((long)(b * 32 + c) * 256) * 1024 + hh * 64;
    const float* kg = g_k + kvbase;
    const float* vg = g_v + kvbase;

    #pragma unroll
    for (int rep = 0; rep < 4; rep++) {
        const int f  = tid + 256 * rep;
        const int qi = f >> 4;
        const int d4 = (f & 15) * 4;
        float4 v = *reinterpret_cast<const float4*>(qg + (long)qi * 1024 + d4);
        qT[(d4 + 0) * 68 + qi] = v.x;
        qT[(d4 + 1) * 68 + qi] = v.y;
        qT[(d4 + 2) * 68 + qi] = v.z;
        qT[(d4 + 3) * 68 + qi] = v.w;
    }
    #pragma unroll
    for (int rep = 0; rep < 16; rep++) {
        const int d4 = rep * 4;
        float4 v = *reinterpret_cast<const float4*>(kg + (long)tid * 1024 + d4);
        kv[(d4 + 0) * 260 + tid] = v.x;
        kv[(d4 + 1) * 260 + tid] = v.y;
        kv[(d4 + 2) * 260 + tid] = v.z;
        kv[(d4 + 3) * 260 + tid] = v.w;
    }
    __syncthreads();

    {
        const int tm = (tid >> 5) << 3;
        const int tn = (tid & 31) << 3;
        float s[8][8];
        #pragma unroll
        for (int i = 0; i < 8; i++)
            #pragma unroll
            for (int j = 0; j < 8; j++) s[i][j] = 0.f;

        #pragma unroll 4
        for (int d = 0; d < 64; d++) {
            float4 a0 = *reinterpret_cast<const float4*>(&qT[d * 68 + tm]);
            float4 a1 = *reinterpret_cast<const float4*>(&qT[d * 68 + tm + 4]);
            float4 b0 = *reinterpret_cast<const float4*>(&kv[d * 260 + tn]);
            float4 b1 = *reinterpret_cast<const float4*>(&kv[d * 260 + tn + 4]);
            float a_[8] = {a0.x, a0.y, a0.z, a0.w, a1.x, a1.y, a1.z, a1.w};
            float b_[8] = {b0.x, b0.y, b0.z, b0.w, b1.x, b1.y, b1.z, b1.w};
            #pragma unroll
            for (int i = 0; i < 8; i++)
                #pragma unroll
                for (int j = 0; j < 8; j++)
                    s[i][j] += a_[i] * b_[j];
        }
        const float SC = 0.125f;
        #pragma unroll
        for (int i = 0; i < 8; i++) {
            float4 s0 = make_float4(s[i][0] * SC, s[i][1] * SC, s[i][2] * SC, s[i][3] * SC);
            float4 s1 = make_float4(s[i][4] * SC, s[i][5] * SC, s[i][6] * SC, s[i][7] * SC);
            *reinterpret_cast<float4*>(&ss[(tm + i) * 260 + tn])     = s0;
            *reinterpret_cast<float4*>(&ss[(tm + i) * 260 + tn + 4]) = s1;
        }
    }
    __syncthreads();

    #pragma unroll
    for (int rep = 0; rep < 16; rep++) {
        const int f  = tid + 256 * rep;
        const int j  = f >> 4;
        const int d4 = (f & 15) * 4;
        float4 v = *reinterpret_cast<const float4*>(vg + (long)j * 1024 + d4);
        *reinterpret_cast<float4*>(&kv[j * 68 + d4]) = v;
    }
    if (tid < 64) {
        float* row = ss + tid * 260;
        float mx = -1e30f;
        #pragma unroll 8
        for (int j = 0; j < 256; j++) mx = fmaxf(mx, row[j]);
        float sum = 0.f;
        #pragma unroll 8
        for (int j = 0; j < 256; j++) {
            float e_ = __expf(row[j] - mx);
            row[j] = e_;
            sum += e_;
        }
        rsum[tid] = 1.0f / sum;
    }
    __syncthreads();

    {
        const int tm2 = (tid >> 4) << 2;
        const int tn2 = (tid & 15) << 2;
        float o[4][4];
        #pragma unroll
        for (int i = 0; i < 4; i++)
            #pragma unroll
            for (int j = 0; j < 4; j++) o[i][j] = 0.f;

        #pragma unroll 4
        for (int j = 0; j < 256; j++) {
            float4 bv = *reinterpret_cast<const float4*>(&kv[j * 68 + tn2]);
            #pragma unroll
            for (int i = 0; i < 4; i++) {
                float a = ss[(tm2 + i) * 260 + j];
                o[i][0] += a * bv.x;
                o[i][1] += a * bv.y;
                o[i][2] += a * bv.z;
                o[i][3] += a * bv.w;
            }
        }
        float* og = g_ao + (long)(b * 2048 + c * 64) * 1024 + hh * 64;
        #pragma unroll
        for (int i = 0; i < 4; i++) {
            const float r = rsum[tm2 + i];
            float4 w = make_float4(o[i][0] * r, o[i][1] * r, o[i][2] * r, o[i][3] * r);
            *reinterpret_cast<float4*>(og + (long)(tm2 + i) * 1024 + tn2) = w;
        }
    }
}

// ---------------------------------------------------------------------------
extern "C" void kernel_launch(void* const* d_in, const int* in_sizes, int n_in,
                              void* d_out, int out_size) {
    (void)in_sizes; (void)n_in; (void)out_size;
    const float* h     = (const float*)d_in[0];
    const float* e     = (const float*)d_in[1];
    const float* Wq    = (const float*)d_in[2];
    const float* bq    = (const float*)d_in[3];
    const float* Wk    = (const float*)d_in[4];
    const float* bk    = (const float*)d_in[5];
    const float* Wv    = (const float*)d_in[6];
    const float* bv    = (const float*)d_in[7];
    const float* Wo    = (const float*)d_in[8];
    const float* bo    = (const float*)d_in[9];
    const float* gamma = (const float*)d_in[10];
    const float* beta  = (const float*)d_in[11];
    float* out = (float*)d_out;

    void *p_hsn, *p_q, *p_k, *p_v, *p_ao, *p_wT;
    cudaGetSymbolAddress(&p_hsn, g_hsn);
    cudaGetSymbolAddress(&p_q,   g_q);
    cudaGetSymbolAddress(&p_k,   g_k);
    cudaGetSymbolAddress(&p_v,   g_v);
    cudaGetSymbolAddress(&p_ao,  g_ao);
    cudaGetSymbolAddress(&p_wT,  g_wT);
    float* wTq = (float*)p_wT;
    float* wTk = wTq + 1024 * 1024;
    float* wTv = wTk + 1024 * 1024;
    float* wTo = wTv + 1024 * 1024;

    cudaFuncSetAttribute(attn_kernel, cudaFuncAttributeMaxDynamicSharedMemorySize,
                         ATT_SMEM_BYTES);
    cudaFuncSetAttribute(mma_gemm<false>, cudaFuncAttributeMaxDynamicSharedMemorySize,
                         GM_SMEM);
    cudaFuncSetAttribute(mma_gemm<true>, cudaFuncAttributeMaxDynamicSharedMemorySize,
                         GM_SMEM);

    // 1. LayerNorm + pad
    ln_kernel<<<4 * 2048, 256>>>(h, gamma, beta);
    // 2. Weight transposes (tf32-rounded)
    transpose_w<<<dim3(32, 32), dim3(32, 8)>>>(Wq, wTq);
    transpose_w<<<dim3(32, 32), dim3(32, 8)>>>(Wk, wTk);
    transpose_w<<<dim3(32, 32), dim3(32, 8)>>>(Wv, wTv);
    transpose_w<<<dim3(32, 32), dim3(32, 8)>>>(Wo, wTo);
    // 3. Q projection
    mma_gemm<false><<<dim3(8, 64),  256, GM_SMEM>>>((const float*)p_hsn, wTq, bq, nullptr, (float*)p_q);
    // 4. K projection
    mma_gemm<false><<<dim3(8, 256), 256, GM_SMEM>>>(e, wTk, bk, nullptr, (float*)p_k);
    // 5. V projection
    mma_gemm<false><<<dim3(8, 256), 256, GM_SMEM>>>(e, wTv, bv, nullptr, (float*)p_v);
    // 6. Attention
    attn_kernel<<<dim3(16, 32, 4), 256, ATT_SMEM_BYTES>>>();
    // 7. Output projection + shift + bias + residual
    mma_gemm<true><<<dim3(8, 64), 256, GM_SMEM>>>((const float*)p_ao, wTo, bo, h, out);
}

// round 4
// speedup vs baseline: 3.2962x; 1.7110x over previous
#include <cuda_runtime.h>
#include <cuda_bf16.h>
#include <cstdint>

// ---------------------------------------------------------------------------
// ChunkedCrossAttention  (B=4, S=2048, D=1024, C=32, N=2, L=128, H=16, DK=64)
// Round 3: projections on bf16 mma.sync m16n8k16 + ldmatrix + cp.async.
//
//   1. ln_kernel        LayerNorm(h[:,63:]) -> g_hsn_bf (bf16, padded)
//   2. cvt_e            e fp32 -> g_e_bf (bf16)
//   3. transpose_w x4   W[k][n] -> WT bf16 [n][k]
//   4. mma_gemm<false>  g_q = hsn @ Wq + bq   (fp32 out)
//   5. mma_gemm<false>  g_k = e @ Wk + bk
//   6. mma_gemm<false>  g_v = e @ Wv + bv
//   7. attn_kernel      softmax(QK^T/8)V -> g_ao_bf (bf16)
//   8. mma_gemm<true>   out = h + shift63(ao @ Wo + bo)
// ---------------------------------------------------------------------------

#define VALID_ROWS 1985

// ---------------- scratch ----------------
__device__ __nv_bfloat16 g_hsn_bf[4 * 2048 * 1024];
__device__ __nv_bfloat16 g_e_bf  [4 * 32 * 256 * 1024];
__device__ __nv_bfloat16 g_ao_bf [4 * 2048 * 1024];
__device__ __nv_bfloat16 g_wT_bf [4 * 1024 * 1024];
__device__ float g_q[4 * 2048 * 1024];
__device__ float g_k[4 * 32 * 256 * 1024];
__device__ float g_v[4 * 32 * 256 * 1024];

// ---------------- helpers ----------------
__device__ __forceinline__ uint32_t smem_u32(const void* p) {
    uint32_t a;
    asm("{ .reg .u64 t; cvta.to.shared.u64 t, %1; cvt.u32.u64 %0, t; }" : "=r"(a) : "l"(p));
    return a;
}
#define CP_ASYNC16(dst, src) \
    asm volatile("cp.async.cg.shared.global [%0], [%1], 16;" :: "r"(dst), "l"(src) : "memory")
#define CP_COMMIT() asm volatile("cp.async.commit_group;" ::: "memory")
#define CP_WAIT(n)  asm volatile("cp.async.wait_group %0;" :: "n"(n) : "memory")

#define LDMATRIX_X4(r0, r1, r2, r3, addr) \
    asm volatile("ldmatrix.sync.aligned.m8n8.x4.shared.b16 {%0,%1,%2,%3}, [%4];" \
                 : "=r"(r0), "=r"(r1), "=r"(r2), "=r"(r3) : "r"(addr))

#define MMA_BF16(c, a, b0, b1) \
    asm volatile("mma.sync.aligned.m16n8k16.row.col.f32.bf16.bf16.f32 " \
                 "{%0,%1,%2,%3}, {%4,%5,%6,%7}, {%8,%9}, {%0,%1,%2,%3};" \
                 : "+f"((c)[0]), "+f"((c)[1]), "+f"((c)[2]), "+f"((c)[3]) \
                 : "r"((a)[0]), "r"((a)[1]), "r"((a)[2]), "r"((a)[3]), \
                   "r"(b0), "r"(b1))

// ---------------------------------------------------------------------------
// 1. LayerNorm -> bf16 (rows t>=VALID zero-padded)
// ---------------------------------------------------------------------------
__global__ void ln_kernel(const float* __restrict__ h,
                          const float* __restrict__ gamma,
                          const float* __restrict__ beta) {
    const int m = blockIdx.x;
    const int b = m >> 11;
    const int t = m & 2047;
    const int tid = threadIdx.x;

    __nv_bfloat162* dst =
        reinterpret_cast<__nv_bfloat162*>(g_hsn_bf + (long)m * 1024 + tid * 4);
    if (t >= VALID_ROWS) {
        __nv_bfloat162 z = __floats2bfloat162_rn(0.f, 0.f);
        dst[0] = z; dst[1] = z;
        return;
    }
    const float4* src =
        reinterpret_cast<const float4*>(h + ((long)(b * 2048 + t + 63)) * 1024) + tid;
    float4 x = *src;

    float s = x.x + x.y + x.z + x.w;
    float q = x.x * x.x + x.y * x.y + x.z * x.z + x.w * x.w;
    #pragma unroll
    for (int o = 16; o > 0; o >>= 1) {
        s += __shfl_xor_sync(0xFFFFFFFFu, s, o);
        q += __shfl_xor_sync(0xFFFFFFFFu, q, o);
    }
    __shared__ float rs[8], rq[8];
    const int w = tid >> 5;
    if ((tid & 31) == 0) { rs[w] = s; rq[w] = q; }
    __syncthreads();
    s = 0.f; q = 0.f;
    #pragma unroll
    for (int i = 0; i < 8; i++) { s += rs[i]; q += rq[i]; }

    const float mu   = s * (1.0f / 1024.0f);
    const float var  = q * (1.0f / 1024.0f) - mu * mu;
    const float rstd = rsqrtf(var + 1e-5f);

    float4 g  = reinterpret_cast<const float4*>(gamma)[tid];
    float4 bb = reinterpret_cast<const float4*>(beta )[tid];
    float ox = (x.x - mu) * rstd * g.x + bb.x;
    float oy = (x.y - mu) * rstd * g.y + bb.y;
    float oz = (x.z - mu) * rstd * g.z + bb.z;
    float ow = (x.w - mu) * rstd * g.w + bb.w;
    dst[0] = __floats2bfloat162_rn(ox, oy);
    dst[1] = __floats2bfloat162_rn(oz, ow);
}

// ---------------------------------------------------------------------------
// 2. e -> bf16 (8 elems / thread)
// ---------------------------------------------------------------------------
__global__ void cvt_e(const float* __restrict__ src) {
    const long i = ((long)blockIdx.x * blockDim.x + threadIdx.x) * 8;
    float4 a = *reinterpret_cast<const float4*>(src + i);
    float4 b = *reinterpret_cast<const float4*>(src + i + 4);
    __nv_bfloat162 o[4];
    o[0] = __floats2bfloat162_rn(a.x, a.y);
    o[1] = __floats2bfloat162_rn(a.z, a.w);
    o[2] = __floats2bfloat162_rn(b.x, b.y);
    o[3] = __floats2bfloat162_rn(b.z, b.w);
    *reinterpret_cast<uint4*>(g_e_bf + i) = *reinterpret_cast<uint4*>(o);
}

// ---------------------------------------------------------------------------
// 3. Transpose: WT[n][k] = bf16(W[k][n])
// ---------------------------------------------------------------------------
__global__ void transpose_w(const float* __restrict__ src, __nv_bfloat16* __restrict__ dst) {
    __shared__ float t[32][33];
    const int x  = blockIdx.x * 32 + threadIdx.x;
    const int y0 = blockIdx.y * 32 + threadIdx.y;
    #pragma unroll
    for (int i = 0; i < 4; i++)
        t[threadIdx.y + 8 * i][threadIdx.x] = src[(long)(y0 + 8 * i) * 1024 + x];
    __syncthreads();
    const int x2  = blockIdx.y * 32 + threadIdx.x;
    const int y20 = blockIdx.x * 32 + threadIdx.y;
    #pragma unroll
    for (int i = 0; i < 4; i++)
        dst[(long)(y20 + 8 * i) * 1024 + x2] =
            __float2bfloat16_rn(t[threadIdx.x][threadIdx.y + 8 * i]);
}

// ---------------------------------------------------------------------------
// 4. bf16 mma GEMM: C[M,1024] = A_bf[M,1024] @ WT^T + bias  (fp32 out)
//    BM=BN=128, BK=64, 256 thr, warp tile 32x64, cp.async 2-stage,
//    ldmatrix fragment loads. Row stride 144B (conflict-free ldmatrix).
// ---------------------------------------------------------------------------
#define SROWB 144                      // bytes per tile row (128 data + 16 pad)
#define TILEB (128 * SROWB)            // 18432 B per tile
#define ASTG  (2 * TILEB)              // stage stride (A+B)
#define GM_SMEM (2 * ASTG)             // 73728 B

template <bool SHIFT>
__global__ void __launch_bounds__(256)
mma_gemm(const __nv_bfloat16* __restrict__ A, const __nv_bfloat16* __restrict__ WT,
         const float* __restrict__ bias, const float* __restrict__ resid,
         float* __restrict__ Cm) {
    extern __shared__ char smemc[];
    const uint32_t sb = smem_u32(smemc);

    const int tid  = threadIdx.x;
    const int wid  = tid >> 5;
    const int lane = tid & 31;
    const int g    = lane >> 2;
    const int tig  = lane & 3;

    const int n0 = blockIdx.x * 128;
    const int m0 = blockIdx.y * 128;
    const int warp_m = (wid & 3) * 32;
    const int warp_n = (wid >> 2) * 64;

    // ---- loader: thread -> row tid>>1, 4 x 16B chunks ----
    const int lrow = tid >> 1;
    const int lc0  = (tid & 1) * 4;                 // chunk index base (of 8)
    const int am   = m0 + lrow;
    bool avalid = true;
    const __nv_bfloat16* aptr;
    if (SHIFT) {
        avalid = (am & 2047) >= 63;
        aptr = avalid ? (A + (long)(am - 63) * 1024) : A;
    } else {
        aptr = A + (long)am * 1024;
    }
    const __nv_bfloat16* bptr = WT + (long)(n0 + lrow) * 1024;
    const uint32_t a_s = sb + (uint32_t)(lrow * SROWB + lc0 * 16);
    const uint32_t b_s = a_s + TILEB;

    auto load_tile = [&](int kt, int s) {
        const uint32_t so = (uint32_t)s * ASTG;
        const __nv_bfloat16* ap = aptr + kt * 64 + lc0 * 8;
        const __nv_bfloat16* bp = bptr + kt * 64 + lc0 * 8;
        if (avalid) {
            #pragma unroll
            for (int i = 0; i < 4; i++) CP_ASYNC16(a_s + so + i * 16, ap + i * 8);
        } else {
            #pragma unroll
            for (int i = 0; i < 4; i++)
                *reinterpret_cast<uint4*>(smemc + (a_s - sb) + so + i * 16) =
                    make_uint4(0, 0, 0, 0);
        }
        #pragma unroll
        for (int i = 0; i < 4; i++) CP_ASYNC16(b_s + so + i * 16, bp + i * 8);
    };

    // ldmatrix per-lane offsets
    const uint32_t aoff = sb + (uint32_t)((warp_m + (lane & 15)) * SROWB + (lane >> 4) * 16);
    const uint32_t boff = sb + TILEB +
        (uint32_t)((warp_n + (lane & 7) + ((lane >> 4) << 3)) * SROWB + ((lane >> 3) & 1) * 16);

    float c[2][8][4];
    #pragma unroll
    for (int mi = 0; mi < 2; mi++)
        #pragma unroll
        for (int ni = 0; ni < 8; ni++)
            #pragma unroll
            for (int r = 0; r < 4; r++) c[mi][ni][r] = 0.f;

    load_tile(0, 0);
    CP_COMMIT();

    #pragma unroll 1
    for (int kt = 0; kt < 16; kt++) {
        const int s = kt & 1;
        if (kt + 1 < 16) {
            load_tile(kt + 1, s ^ 1);
            CP_COMMIT();
            CP_WAIT(1);
        } else {
            CP_WAIT(0);
        }
        __syncthreads();

        const uint32_t so = (uint32_t)s * ASTG;
        #pragma unroll
        for (int ks = 0; ks < 4; ks++) {
            uint32_t a[2][4];
            #pragma unroll
            for (int mi = 0; mi < 2; mi++)
                LDMATRIX_X4(a[mi][0], a[mi][1], a[mi][2], a[mi][3],
                            aoff + so + mi * (16 * SROWB) + ks * 32);
            uint32_t b[4][4];
            #pragma unroll
            for (int nb = 0; nb < 4; nb++)
                LDMATRIX_X4(b[nb][0], b[nb][1], b[nb][2], b[nb][3],
                            boff + so + nb * (16 * SROWB) + ks * 32);
            #pragma unroll
            for (int mi = 0; mi < 2; mi++)
                #pragma unroll
                for (int nb = 0; nb < 4; nb++) {
                    MMA_BF16(c[mi][nb * 2 + 0], a[mi], b[nb][0], b[nb][1]);
                    MMA_BF16(c[mi][nb * 2 + 1], a[mi], b[nb][2], b[nb][3]);
                }
        }
        __syncthreads();
    }

    // ---- epilogue ----
    #pragma unroll
    for (int mi = 0; mi < 2; mi++) {
        const int r0 = m0 + warp_m + mi * 16 + g;
        const int r1 = r0 + 8;
        #pragma unroll
        for (int ni = 0; ni < 8; ni++) {
            const int col = n0 + warp_n + ni * 8 + 2 * tig;
            float2 bs = *reinterpret_cast<const float2*>(bias + col);
            float2 o0 = make_float2(c[mi][ni][0], c[mi][ni][1]);
            float2 o1 = make_float2(c[mi][ni][2], c[mi][ni][3]);
            if (SHIFT) {
                float2 rv0 = *reinterpret_cast<const float2*>(resid + (long)r0 * 1024 + col);
                float2 rv1 = *reinterpret_cast<const float2*>(resid + (long)r1 * 1024 + col);
                if ((r0 & 2047) >= 63) {
                    o0.x += bs.x + rv0.x; o0.y += bs.y + rv0.y;
                } else o0 = rv0;
                if ((r1 & 2047) >= 63) {
                    o1.x += bs.x + rv1.x; o1.y += bs.y + rv1.y;
                } else o1 = rv1;
            } else {
                o0.x += bs.x; o0.y += bs.y;
                o1.x += bs.x; o1.y += bs.y;
            }
            *reinterpret_cast<float2*>(Cm + (long)r0 * 1024 + col) = o0;
            *reinterpret_cast<float2*>(Cm + (long)r1 * 1024 + col) = o1;
        }
    }
}

// ---------------------------------------------------------------------------
// 7. Attention: one block per (b, c, h), 256 threads; bf16 output.
// ---------------------------------------------------------------------------
#define ATT_SMEM_FLOATS (4352 + 16640 + 17408 + 64)
#define ATT_SMEM_BYTES  (ATT_SMEM_FLOATS * 4)

__global__ void attn_kernel() {
    extern __shared__ float sm[];
    float* qT   = sm;
    float* ss   = sm + 4352;
    float* kv   = sm + 4352 + 16640;
    float* rsum = sm + 4352 + 16640 + 17408;

    const int tid = threadIdx.x;
    const int hh = blockIdx.x, c = blockIdx.y, b = blockIdx.z;

    const float* qg = g_q + (long)(b * 2048 + c * 64) * 1024 + hh * 64;
    const long  kvbase = ((long)(b * 32 + c) * 256) * 1024 + hh * 64;
    const float* kg = g_k + kvbase;
    const float* vg = g_v + kvbase;

    #pragma unroll
    for (int rep = 0; rep < 4; rep++) {
        const int f  = tid + 256 * rep;
        const int qi = f >> 4;
        const int d4 = (f & 15) * 4;
        float4 v = *reinterpret_cast<const float4*>(qg + (long)qi * 1024 + d4);
        qT[(d4 + 0) * 68 + qi] = v.x;
        qT[(d4 + 1) * 68 + qi] = v.y;
        qT[(d4 + 2) * 68 + qi] = v.z;
        qT[(d4 + 3) * 68 + qi] = v.w;
    }
    #pragma unroll
    for (int rep = 0; rep < 16; rep++) {
        const int d4 = rep * 4;
        float4 v = *reinterpret_cast<const float4*>(kg + (long)tid * 1024 + d4);
        kv[(d4 + 0) * 260 + tid] = v.x;
        kv[(d4 + 1) * 260 + tid] = v.y;
        kv[(d4 + 2) * 260 + tid] = v.z;
        kv[(d4 + 3) * 260 + tid] = v.w;
    }
    __syncthreads();

    {
        const int tm = (tid >> 5) << 3;
        const int tn = (tid & 31) << 3;
        float s[8][8];
        #pragma unroll
        for (int i = 0; i < 8; i++)
            #pragma unroll
            for (int j = 0; j < 8; j++) s[i][j] = 0.f;

        #pragma unroll 4
        for (int d = 0; d < 64; d++) {
            float4 a0 = *reinterpret_cast<const float4*>(&qT[d * 68 + tm]);
            float4 a1 = *reinterpret_cast<const float4*>(&qT[d * 68 + tm + 4]);
            float4 b0 = *reinterpret_cast<const float4*>(&kv[d * 260 + tn]);
            float4 b1 = *reinterpret_cast<const float4*>(&kv[d * 260 + tn + 4]);
            float a_[8] = {a0.x, a0.y, a0.z, a0.w, a1.x, a1.y, a1.z, a1.w};
            float b_[8] = {b0.x, b0.y, b0.z, b0.w, b1.x, b1.y, b1.z, b1.w};
            #pragma unroll
            for (int i = 0; i < 8; i++)
                #pragma unroll
                for (int j = 0; j < 8; j++)
                    s[i][j] += a_[i] * b_[j];
        }
        const float SC = 0.125f;
        #pragma unroll
        for (int i = 0; i < 8; i++) {
            float4 s0 = make_float4(s[i][0] * SC, s[i][1] * SC, s[i][2] * SC, s[i][3] * SC);
            float4 s1 = make_float4(s[i][4] * SC, s[i][5] * SC, s[i][6] * SC, s[i][7] * SC);
            *reinterpret_cast<float4*>(&ss[(tm + i) * 260 + tn])     = s0;
            *reinterpret_cast<float4*>(&ss[(tm + i) * 260 + tn + 4]) = s1;
        }
    }
    __syncthreads();

    #pragma unroll
    for (int rep = 0; rep < 16; rep++) {
        const int f  = tid + 256 * rep;
        const int j  = f >> 4;
        const int d4 = (f & 15) * 4;
        float4 v = *reinterpret_cast<const float4*>(vg + (long)j * 1024 + d4);
        *reinterpret_cast<float4*>(&kv[j * 68 + d4]) = v;
    }
    if (tid < 64) {
        float* row = ss + tid * 260;
        float mx = -1e30f;
        #pragma unroll 8
        for (int j = 0; j < 256; j++) mx = fmaxf(mx, row[j]);
        float sum = 0.f;
        #pragma unroll 8
        for (int j = 0; j < 256; j++) {
            float e_ = __expf(row[j] - mx);
            row[j] = e_;
            sum += e_;
        }
        rsum[tid] = 1.0f / sum;
    }
    __syncthreads();

    {
        const int tm2 = (tid >> 4) << 2;
        const int tn2 = (tid & 15) << 2;
        float o[4][4];
        #pragma unroll
        for (int i = 0; i < 4; i++)
            #pragma unroll
            for (int j = 0; j < 4; j++) o[i][j] = 0.f;

        #pragma unroll 4
        for (int j = 0; j < 256; j++) {
            float4 bv = *reinterpret_cast<const float4*>(&kv[j * 68 + tn2]);
            #pragma unroll
            for (int i = 0; i < 4; i++) {
                float a = ss[(tm2 + i) * 260 + j];
                o[i][0] += a * bv.x;
                o[i][1] += a * bv.y;
                o[i][2] += a * bv.z;
                o[i][3] += a * bv.w;
            }
        }
        __nv_bfloat16* og = g_ao_bf + (long)(b * 2048 + c * 64) * 1024 + hh * 64;
        #pragma unroll
        for (int i = 0; i < 4; i++) {
            const float r = rsum[tm2 + i];
            __nv_bfloat162 w0 = __floats2bfloat162_rn(o[i][0] * r, o[i][1] * r);
            __nv_bfloat162 w1 = __floats2bfloat162_rn(o[i][2] * r, o[i][3] * r);
            __nv_bfloat162* p =
                reinterpret_cast<__nv_bfloat162*>(og + (long)(tm2 + i) * 1024 + tn2);
            p[0] = w0; p[1] = w1;
        }
    }
}

// ---------------------------------------------------------------------------
extern "C" void kernel_launch(void* const* d_in, const int* in_sizes, int n_in,
                              void* d_out, int out_size) {
    (void)in_sizes; (void)n_in; (void)out_size;
    const float* h     = (const float*)d_in[0];
    const float* e     = (const float*)d_in[1];
    const float* Wq    = (const float*)d_in[2];
    const float* bq    = (const float*)d_in[3];
    const float* Wk    = (const float*)d_in[4];
    const float* bk    = (const float*)d_in[5];
    const float* Wv    = (const float*)d_in[6];
    const float* bv    = (const float*)d_in[7];
    const float* Wo    = (const float*)d_in[8];
    const float* bo    = (const float*)d_in[9];
    const float* gamma = (const float*)d_in[10];
    const float* beta  = (const float*)d_in[11];
    float* out = (float*)d_out;

    void *p_hsn, *p_e, *p_ao, *p_wT, *p_q, *p_k, *p_v;
    cudaGetSymbolAddress(&p_hsn, g_hsn_bf);
    cudaGetSymbolAddress(&p_e,   g_e_bf);
    cudaGetSymbolAddress(&p_ao,  g_ao_bf);
    cudaGetSymbolAddress(&p_wT,  g_wT_bf);
    cudaGetSymbolAddress(&p_q,   g_q);
    cudaGetSymbolAddress(&p_k,   g_k);
    cudaGetSymbolAddress(&p_v,   g_v);
    __nv_bfloat16* wTq = (__nv_bfloat16*)p_wT;
    __nv_bfloat16* wTk = wTq + 1024 * 1024;
    __nv_bfloat16* wTv = wTk + 1024 * 1024;
    __nv_bfloat16* wTo = wTv + 1024 * 1024;

    cudaFuncSetAttribute(attn_kernel, cudaFuncAttributeMaxDynamicSharedMemorySize,
                         ATT_SMEM_BYTES);
    cudaFuncSetAttribute(mma_gemm<false>, cudaFuncAttributeMaxDynamicSharedMemorySize,
                         GM_SMEM);
    cudaFuncSetAttribute(mma_gemm<true>, cudaFuncAttributeMaxDynamicSharedMemorySize,
                         GM_SMEM);

    // 1. LayerNorm -> bf16
    ln_kernel<<<4 * 2048, 256>>>(h, gamma, beta);
    // 2. e -> bf16
    cvt_e<<<16384, 256>>>(e);
    // 3. Weight transposes -> bf16
    transpose_w<<<dim3(32, 32), dim3(32, 8)>>>(Wq, wTq);
    transpose_w<<<dim3(32, 32), dim3(32, 8)>>>(Wk, wTk);
    transpose_w<<<dim3(32, 32), dim3(32, 8)>>>(Wv, wTv);
    transpose_w<<<dim3(32, 32), dim3(32, 8)>>>(Wo, wTo);
    // 4-6. Projections
    mma_gemm<false><<<dim3(8, 64),  256, GM_SMEM>>>((const __nv_bfloat16*)p_hsn, wTq, bq, nullptr, (float*)p_q);
    mma_gemm<false><<<dim3(8, 256), 256, GM_SMEM>>>((const __nv_bfloat16*)p_e, wTk, bk, nullptr, (float*)p_k);
    mma_gemm<false><<<dim3(8, 256), 256, GM_SMEM>>>((const __nv_bfloat16*)p_e, wTv, bv, nullptr, (float*)p_v);
    // 7. Attention
    attn_kernel<<<dim3(16, 32, 4), 256, ATT_SMEM_BYTES>>>();
    // 8. Output projection + shift + bias + residual
    mma_gemm<true><<<dim3(8, 64), 256, GM_SMEM>>>((const __nv_bfloat16*)p_ao, wTo, bo, h, out);
}

// round 6
// speedup vs baseline: 4.2135x; 1.2783x over previous
#include <cuda_runtime.h>
#include <cuda_bf16.h>
#include <cuda_fp16.h>
#include <cstdint>

// ---------------------------------------------------------------------------
// ChunkedCrossAttention  (B=4, S=2048, D=1024, C=32, N=2, L=128, H=16, DK=64)
// Round 5 = Round 4 resubmitted verbatim (R4 bench was an infra flake:
// "GB300 container failed twice" — no kernel signal).
// Tensor-core flash attention (fp16 mma, in-register softmax, poly exp);
// projections bf16 mma; Q/K/V stored fp16.
// ---------------------------------------------------------------------------

#define VALID_ROWS 1985

// ---------------- scratch ----------------
__device__ __nv_bfloat16 g_hsn_bf[4 * 2048 * 1024];
__device__ __nv_bfloat16 g_e_bf  [4 * 32 * 256 * 1024];
__device__ __nv_bfloat16 g_ao_bf [4 * 2048 * 1024];
__device__ __nv_bfloat16 g_wT_bf [4 * 1024 * 1024];
__device__ __half g_q_h[4 * 2048 * 1024];
__device__ __half g_k_h[4 * 32 * 256 * 1024];
__device__ __half g_v_h[4 * 32 * 256 * 1024];

// ---------------- helpers ----------------
__device__ __forceinline__ uint32_t smem_u32(const void* p) {
    uint32_t a;
    asm("{ .reg .u64 t; cvta.to.shared.u64 t, %1; cvt.u32.u64 %0, t; }" : "=r"(a) : "l"(p));
    return a;
}
#define CP_ASYNC16(dst, src) \
    asm volatile("cp.async.cg.shared.global [%0], [%1], 16;" :: "r"(dst), "l"(src) : "memory")
#define CP_COMMIT() asm volatile("cp.async.commit_group;" ::: "memory")
#define CP_WAIT(n)  asm volatile("cp.async.wait_group %0;" :: "n"(n) : "memory")

#define LDMATRIX_X4(r0, r1, r2, r3, addr) \
    asm volatile("ldmatrix.sync.aligned.m8n8.x4.shared.b16 {%0,%1,%2,%3}, [%4];" \
                 : "=r"(r0), "=r"(r1), "=r"(r2), "=r"(r3) : "r"(addr))
#define LDMATRIX_X4_TRANS(r0, r1, r2, r3, addr) \
    asm volatile("ldmatrix.sync.aligned.m8n8.x4.trans.shared.b16 {%0,%1,%2,%3}, [%4];" \
                 : "=r"(r0), "=r"(r1), "=r"(r2), "=r"(r3) : "r"(addr))

#define MMA_BF16(c, a, b0, b1) \
    asm volatile("mma.sync.aligned.m16n8k16.row.col.f32.bf16.bf16.f32 " \
                 "{%0,%1,%2,%3}, {%4,%5,%6,%7}, {%8,%9}, {%0,%1,%2,%3};" \
                 : "+f"((c)[0]), "+f"((c)[1]), "+f"((c)[2]), "+f"((c)[3]) \
                 : "r"((a)[0]), "r"((a)[1]), "r"((a)[2]), "r"((a)[3]), \
                   "r"(b0), "r"(b1))
#define MMA_F16(c, a, b0, b1) \
    asm volatile("mma.sync.aligned.m16n8k16.row.col.f32.f16.f16.f32 " \
                 "{%0,%1,%2,%3}, {%4,%5,%6,%7}, {%8,%9}, {%0,%1,%2,%3};" \
                 : "+f"((c)[0]), "+f"((c)[1]), "+f"((c)[2]), "+f"((c)[3]) \
                 : "r"((a)[0]), "r"((a)[1]), "r"((a)[2]), "r"((a)[3]), \
                   "r"(b0), "r"(b1))

__device__ __forceinline__ uint32_t pack_h2(float x, float y) {
    __half2 h = __floats2half2_rn(x, y);
    return *reinterpret_cast<uint32_t*>(&h);
}
// 2^y via range reduction + deg-4 Taylor (rel err ~4e-5, << fp16 rounding)
__device__ __forceinline__ float fexp2(float y) {
    y = fmaxf(y, -80.f);
    float r = rintf(y);
    float f = y - r;
    float p = 1.f + f * (0.693147182f + f * (0.240226512f +
              f * (0.0555041087f + f * 0.00961812911f)));
    return p * __int_as_float(((int)r + 127) << 23);
}

// ---------------------------------------------------------------------------
// 1. LayerNorm -> bf16 (rows t>=VALID zero-padded)
// ---------------------------------------------------------------------------
__global__ void ln_kernel(const float* __restrict__ h,
                          const float* __restrict__ gamma,
                          const float* __restrict__ beta) {
    const int m = blockIdx.x;
    const int b = m >> 11;
    const int t = m & 2047;
    const int tid = threadIdx.x;

    __nv_bfloat162* dst =
        reinterpret_cast<__nv_bfloat162*>(g_hsn_bf + (long)m * 1024 + tid * 4);
    if (t >= VALID_ROWS) {
        __nv_bfloat162 z = __floats2bfloat162_rn(0.f, 0.f);
        dst[0] = z; dst[1] = z;
        return;
    }
    const float4* src =
        reinterpret_cast<const float4*>(h + ((long)(b * 2048 + t + 63)) * 1024) + tid;
    float4 x = *src;

    float s = x.x + x.y + x.z + x.w;
    float q = x.x * x.x + x.y * x.y + x.z * x.z + x.w * x.w;
    #pragma unroll
    for (int o = 16; o > 0; o >>= 1) {
        s += __shfl_xor_sync(0xFFFFFFFFu, s, o);
        q += __shfl_xor_sync(0xFFFFFFFFu, q, o);
    }
    __shared__ float rs[8], rq[8];
    const int w = tid >> 5;
    if ((tid & 31) == 0) { rs[w] = s; rq[w] = q; }
    __syncthreads();
    s = 0.f; q = 0.f;
    #pragma unroll
    for (int i = 0; i < 8; i++) { s += rs[i]; q += rq[i]; }

    const float mu   = s * (1.0f / 1024.0f);
    const float var  = q * (1.0f / 1024.0f) - mu * mu;
    const float rstd = rsqrtf(var + 1e-5f);

    float4 g  = reinterpret_cast<const float4*>(gamma)[tid];
    float4 bb = reinterpret_cast<const float4*>(beta )[tid];
    float ox = (x.x - mu) * rstd * g.x + bb.x;
    float oy = (x.y - mu) * rstd * g.y + bb.y;
    float oz = (x.z - mu) * rstd * g.z + bb.z;
    float ow = (x.w - mu) * rstd * g.w + bb.w;
    dst[0] = __floats2bfloat162_rn(ox, oy);
    dst[1] = __floats2bfloat162_rn(oz, ow);
}

// ---------------------------------------------------------------------------
// 2. e -> bf16
// ---------------------------------------------------------------------------
__global__ void cvt_e(const float* __restrict__ src) {
    const long i = ((long)blockIdx.x * blockDim.x + threadIdx.x) * 8;
    float4 a = *reinterpret_cast<const float4*>(src + i);
    float4 b = *reinterpret_cast<const float4*>(src + i + 4);
    __nv_bfloat162 o[4];
    o[0] = __floats2bfloat162_rn(a.x, a.y);
    o[1] = __floats2bfloat162_rn(a.z, a.w);
    o[2] = __floats2bfloat162_rn(b.x, b.y);
    o[3] = __floats2bfloat162_rn(b.z, b.w);
    *reinterpret_cast<uint4*>(g_e_bf + i) = *reinterpret_cast<uint4*>(o);
}

// ---------------------------------------------------------------------------
// 3. Transpose: WT[n][k] = bf16(W[k][n])
// ---------------------------------------------------------------------------
__global__ void transpose_w(const float* __restrict__ src, __nv_bfloat16* __restrict__ dst) {
    __shared__ float t[32][33];
    const int x  = blockIdx.x * 32 + threadIdx.x;
    const int y0 = blockIdx.y * 32 + threadIdx.y;
    #pragma unroll
    for (int i = 0; i < 4; i++)
        t[threadIdx.y + 8 * i][threadIdx.x] = src[(long)(y0 + 8 * i) * 1024 + x];
    __syncthreads();
    const int x2  = blockIdx.y * 32 + threadIdx.x;
    const int y20 = blockIdx.x * 32 + threadIdx.y;
    #pragma unroll
    for (int i = 0; i < 4; i++)
        dst[(long)(y20 + 8 * i) * 1024 + x2] =
            __float2bfloat16_rn(t[threadIdx.x][threadIdx.y + 8 * i]);
}

// ---------------------------------------------------------------------------
// 4. bf16 mma GEMM (as R3). HALFOUT: store __half (Q/K/V); else fp32.
// ---------------------------------------------------------------------------
#define SROWB 144
#define TILEB (128 * SROWB)
#define ASTG  (2 * TILEB)
#define GM_SMEM (2 * ASTG)

template <bool SHIFT, bool HALFOUT>
__global__ void __launch_bounds__(256)
mma_gemm(const __nv_bfloat16* __restrict__ A, const __nv_bfloat16* __restrict__ WT,
         const float* __restrict__ bias, const float* __restrict__ resid,
         void* __restrict__ Cout) {
    extern __shared__ char smemc[];
    const uint32_t sb = smem_u32(smemc);

    const int tid  = threadIdx.x;
    const int wid  = tid >> 5;
    const int lane = tid & 31;
    const int g    = lane >> 2;
    const int tig  = lane & 3;

    const int n0 = blockIdx.x * 128;
    const int m0 = blockIdx.y * 128;
    const int warp_m = (wid & 3) * 32;
    const int warp_n = (wid >> 2) * 64;

    const int lrow = tid >> 1;
    const int lc0  = (tid & 1) * 4;
    const int am   = m0 + lrow;
    bool avalid = true;
    const __nv_bfloat16* aptr;
    if (SHIFT) {
        avalid = (am & 2047) >= 63;
        aptr = avalid ? (A + (long)(am - 63) * 1024) : A;
    } else {
        aptr = A + (long)am * 1024;
    }
    const __nv_bfloat16* bptr = WT + (long)(n0 + lrow) * 1024;
    const uint32_t a_s = sb + (uint32_t)(lrow * SROWB + lc0 * 16);
    const uint32_t b_s = a_s + TILEB;

    auto load_tile = [&](int kt, int s) {
        const uint32_t so = (uint32_t)s * ASTG;
        const __nv_bfloat16* ap = aptr + kt * 64 + lc0 * 8;
        const __nv_bfloat16* bp = bptr + kt * 64 + lc0 * 8;
        if (avalid) {
            #pragma unroll
            for (int i = 0; i < 4; i++) CP_ASYNC16(a_s + so + i * 16, ap + i * 8);
        } else {
            #pragma unroll
            for (int i = 0; i < 4; i++)
                *reinterpret_cast<uint4*>(smemc + (a_s - sb) + so + i * 16) =
                    make_uint4(0, 0, 0, 0);
        }
        #pragma unroll
        for (int i = 0; i < 4; i++) CP_ASYNC16(b_s + so + i * 16, bp + i * 8);
    };

    const uint32_t aoff = sb + (uint32_t)((warp_m + (lane & 15)) * SROWB + (lane >> 4) * 16);
    const uint32_t boff = sb + TILEB +
        (uint32_t)((warp_n + (lane & 7) + ((lane >> 4) << 3)) * SROWB + ((lane >> 3) & 1) * 16);

    float c[2][8][4];
    #pragma unroll
    for (int mi = 0; mi < 2; mi++)
        #pragma unroll
        for (int ni = 0; ni < 8; ni++)
            #pragma unroll
            for (int r = 0; r < 4; r++) c[mi][ni][r] = 0.f;

    load_tile(0, 0);
    CP_COMMIT();

    #pragma unroll 1
    for (int kt = 0; kt < 16; kt++) {
        const int s = kt & 1;
        if (kt + 1 < 16) {
            load_tile(kt + 1, s ^ 1);
            CP_COMMIT();
            CP_WAIT(1);
        } else {
            CP_WAIT(0);
        }
        __syncthreads();

        const uint32_t so = (uint32_t)s * ASTG;
        #pragma unroll
        for (int ks = 0; ks < 4; ks++) {
            uint32_t a[2][4];
            #pragma unroll
            for (int mi = 0; mi < 2; mi++)
                LDMATRIX_X4(a[mi][0], a[mi][1], a[mi][2], a[mi][3],
                            aoff + so + mi * (16 * SROWB) + ks * 32);
            uint32_t b[4][4];
            #pragma unroll
            for (int nb = 0; nb < 4; nb++)
                LDMATRIX_X4(b[nb][0], b[nb][1], b[nb][2], b[nb][3],
                            boff + so + nb * (16 * SROWB) + ks * 32);
            #pragma unroll
            for (int mi = 0; mi < 2; mi++)
                #pragma unroll
                for (int nb = 0; nb < 4; nb++) {
                    MMA_BF16(c[mi][nb * 2 + 0], a[mi], b[nb][0], b[nb][1]);
                    MMA_BF16(c[mi][nb * 2 + 1], a[mi], b[nb][2], b[nb][3]);
                }
        }
        __syncthreads();
    }

    // ---- epilogue ----
    #pragma unroll
    for (int mi = 0; mi < 2; mi++) {
        const int r0 = m0 + warp_m + mi * 16 + g;
        const int r1 = r0 + 8;
        #pragma unroll
        for (int ni = 0; ni < 8; ni++) {
            const int col = n0 + warp_n + ni * 8 + 2 * tig;
            float2 bs = *reinterpret_cast<const float2*>(bias + col);
            float2 o0 = make_float2(c[mi][ni][0] + bs.x, c[mi][ni][1] + bs.y);
            float2 o1 = make_float2(c[mi][ni][2] + bs.x, c[mi][ni][3] + bs.y);
            if (HALFOUT) {
                __half* Cm = (__half*)Cout;
                *reinterpret_cast<__half2*>(Cm + (long)r0 * 1024 + col) =
                    __floats2half2_rn(o0.x, o0.y);
                *reinterpret_cast<__half2*>(Cm + (long)r1 * 1024 + col) =
                    __floats2half2_rn(o1.x, o1.y);
            } else {
                float* Cm = (float*)Cout;
                if (SHIFT) {
                    float2 rv0 = *reinterpret_cast<const float2*>(resid + (long)r0 * 1024 + col);
                    float2 rv1 = *reinterpret_cast<const float2*>(resid + (long)r1 * 1024 + col);
                    if ((r0 & 2047) >= 63) { o0.x += rv0.x; o0.y += rv0.y; }
                    else o0 = rv0;
                    if ((r1 & 2047) >= 63) { o1.x += rv1.x; o1.y += rv1.y; }
                    else o1 = rv1;
                }
                *reinterpret_cast<float2*>(Cm + (long)r0 * 1024 + col) = o0;
                *reinterpret_cast<float2*>(Cm + (long)r1 * 1024 + col) = o1;
            }
        }
    }
}

// ---------------------------------------------------------------------------
// 5. Flash attention: block = (h, c, b), 128 threads (4 warps x 16 queries).
//    fp16 mma QK^T + PV, in-register softmax, poly exp. Output bf16.
// smem rows stride 144B: Q 64, K 256, V 256 -> 82944 B.
// ---------------------------------------------------------------------------
#define AT_SMEM 82944

__global__ void __launch_bounds__(128) attn_kernel() {
    extern __shared__ char smc[];
    const uint32_t sb = smem_u32(smc);
    const uint32_t Qs = sb;
    const uint32_t Ks = sb + 64 * 144;
    const uint32_t Vs = Ks + 256 * 144;

    const int tid  = threadIdx.x;
    const int wid  = tid >> 5;
    const int lane = tid & 31;
    const int g    = lane >> 2;
    const int tig  = lane & 3;
    const int hh = blockIdx.x, cc = blockIdx.y, b = blockIdx.z;

    const __half* qg = g_q_h + ((long)(b * 2048 + cc * 64)) * 1024 + hh * 64;
    const long kvr = ((long)(b * 32 + cc)) * 256;
    const __half* kg = g_k_h + kvr * 1024 + hh * 64;
    const __half* vg = g_v_h + kvr * 1024 + hh * 64;

    // ---- loads ----
    {
        const int row = tid >> 1, hf = tid & 1;
        const uint32_t dst = Qs + row * 144 + hf * 64;
        const __half* src = qg + (long)row * 1024 + hf * 32;
        CP_ASYNC16(dst,      src);
        CP_ASYNC16(dst + 16, src + 8);
        CP_ASYNC16(dst + 32, src + 16);
        CP_ASYNC16(dst + 48, src + 24);
    }
    #pragma unroll
    for (int r = 0; r < 2; r++) {
        const int row = tid * 2 + r;
        const uint32_t dk = Ks + row * 144;
        const uint32_t dv = Vs + row * 144;
        const __half* sk = kg + (long)row * 1024;
        const __half* sv = vg + (long)row * 1024;
        #pragma unroll
        for (int i = 0; i < 8; i++) {
            CP_ASYNC16(dk + i * 16, sk + i * 8);
            CP_ASYNC16(dv + i * 16, sv + i * 8);
        }
    }
    CP_COMMIT();
    CP_WAIT(0);
    __syncthreads();

    // ---- S = Q K^T  (per warp: 16 queries x 256 keys) ----
    float c[32][4];
    #pragma unroll
    for (int ni = 0; ni < 32; ni++)
        #pragma unroll
        for (int r = 0; r < 4; r++) c[ni][r] = 0.f;

    const uint32_t aaddr = Qs + (wid * 16 + (lane & 15)) * 144 + (lane >> 4) * 16;
    const uint32_t baddr = Ks + ((lane & 7) + ((lane >> 4) << 3)) * 144 + ((lane >> 3) & 1) * 16;

    #pragma unroll
    for (int ks = 0; ks < 4; ks++) {
        uint32_t a[4];
        LDMATRIX_X4(a[0], a[1], a[2], a[3], aaddr + ks * 32);
        #pragma unroll
        for (int jt = 0; jt < 16; jt++) {
            uint32_t bb[4];
            LDMATRIX_X4(bb[0], bb[1], bb[2], bb[3], baddr + jt * 2304 + ks * 32);
            MMA_F16(c[2 * jt],     a, bb[0], bb[1]);
            MMA_F16(c[2 * jt + 1], a, bb[2], bb[3]);
        }
    }

    // ---- softmax in registers (rows g and g+8; quad lanes share a row) ----
    float m0 = -1e30f, m1 = -1e30f;
    #pragma unroll
    for (int ni = 0; ni < 32; ni++) {
        m0 = fmaxf(m0, fmaxf(c[ni][0], c[ni][1]));
        m1 = fmaxf(m1, fmaxf(c[ni][2], c[ni][3]));
    }
    m0 = fmaxf(m0, __shfl_xor_sync(0xFFFFFFFFu, m0, 1));
    m0 = fmaxf(m0, __shfl_xor_sync(0xFFFFFFFFu, m0, 2));
    m1 = fmaxf(m1, __shfl_xor_sync(0xFFFFFFFFu, m1, 1));
    m1 = fmaxf(m1, __shfl_xor_sync(0xFFFFFFFFu, m1, 2));

    const float kk = 0.18033688011112042f;   // SCALE * log2(e) = log2(e)/8
    float s0 = 0.f, s1 = 0.f;
    #pragma unroll
    for (int ni = 0; ni < 32; ni++) {
        c[ni][0] = fexp2((c[ni][0] - m0) * kk); s0 += c[ni][0];
        c[ni][1] = fexp2((c[ni][1] - m0) * kk); s0 += c[ni][1];
        c[ni][2] = fexp2((c[ni][2] - m1) * kk); s1 += c[ni][2];
        c[ni][3] = fexp2((c[ni][3] - m1) * kk); s1 += c[ni][3];
    }
    s0 += __shfl_xor_sync(0xFFFFFFFFu, s0, 1);
    s0 += __shfl_xor_sync(0xFFFFFFFFu, s0, 2);
    s1 += __shfl_xor_sync(0xFFFFFFFFu, s1, 1);
    s1 += __shfl_xor_sync(0xFFFFFFFFu, s1, 2);
    const float inv0 = 1.f / s0, inv1 = 1.f / s1;

    // ---- repack P: C-fragment layout == A-fragment layout ----
    uint32_t aP[16][4];
    #pragma unroll
    for (int kc = 0; kc < 16; kc++) {
        aP[kc][0] = pack_h2(c[2 * kc][0],     c[2 * kc][1]);
        aP[kc][1] = pack_h2(c[2 * kc][2],     c[2 * kc][3]);
        aP[kc][2] = pack_h2(c[2 * kc + 1][0], c[2 * kc + 1][1]);
        aP[kc][3] = pack_h2(c[2 * kc + 1][2], c[2 * kc + 1][3]);
    }

    // ---- O = P V  (V via ldmatrix.trans) ----
    float o[8][4];
    #pragma unroll
    for (int nt = 0; nt < 8; nt++)
        #pragma unroll
        for (int r = 0; r < 4; r++) o[nt][r] = 0.f;

    const uint32_t vaddr = Vs + (lane & 15) * 144 + (lane >> 4) * 16;
    #pragma unroll
    for (int kc = 0; kc < 16; kc++) {
        #pragma unroll
        for (int ngi = 0; ngi < 4; ngi++) {
            uint32_t bb[4];
            LDMATRIX_X4_TRANS(bb[0], bb[1], bb[2], bb[3],
                              vaddr + kc * 2304 + ngi * 32);
            MMA_F16(o[2 * ngi],     aP[kc], bb[0], bb[1]);
            MMA_F16(o[2 * ngi + 1], aP[kc], bb[2], bb[3]);
        }
    }

    // ---- store (normalize rows) ----
    __nv_bfloat16* og = g_ao_bf + ((long)(b * 2048 + cc * 64 + wid * 16)) * 1024 + hh * 64;
    #pragma unroll
    for (int nt = 0; nt < 8; nt++) {
        const int col = nt * 8 + tig * 2;
        *reinterpret_cast<__nv_bfloat162*>(og + (long)g * 1024 + col) =
            __floats2bfloat162_rn(o[nt][0] * inv0, o[nt][1] * inv0);
        *reinterpret_cast<__nv_bfloat162*>(og + (long)(g + 8) * 1024 + col) =
            __floats2bfloat162_rn(o[nt][2] * inv1, o[nt][3] * inv1);
    }
}

// ---------------------------------------------------------------------------
extern "C" void kernel_launch(void* const* d_in, const int* in_sizes, int n_in,
                              void* d_out, int out_size) {
    (void)in_sizes; (void)n_in; (void)out_size;
    const float* h     = (const float*)d_in[0];
    const float* e     = (const float*)d_in[1];
    const float* Wq    = (const float*)d_in[2];
    const float* bq    = (const float*)d_in[3];
    const float* Wk    = (const float*)d_in[4];
    const float* bk    = (const float*)d_in[5];
    const float* Wv    = (const float*)d_in[6];
    const float* bv    = (const float*)d_in[7];
    const float* Wo    = (const float*)d_in[8];
    const float* bo    = (const float*)d_in[9];
    const float* gamma = (const float*)d_in[10];
    const float* beta  = (const float*)d_in[11];
    float* out = (float*)d_out;

    void *p_hsn, *p_e, *p_ao, *p_wT, *p_q, *p_k, *p_v;
    cudaGetSymbolAddress(&p_hsn, g_hsn_bf);
    cudaGetSymbolAddress(&p_e,   g_e_bf);
    cudaGetSymbolAddress(&p_ao,  g_ao_bf);
    cudaGetSymbolAddress(&p_wT,  g_wT_bf);
    cudaGetSymbolAddress(&p_q,   g_q_h);
    cudaGetSymbolAddress(&p_k,   g_k_h);
    cudaGetSymbolAddress(&p_v,   g_v_h);
    __nv_bfloat16* wTq = (__nv_bfloat16*)p_wT;
    __nv_bfloat16* wTk = wTq + 1024 * 1024;
    __nv_bfloat16* wTv = wTk + 1024 * 1024;
    __nv_bfloat16* wTo = wTv + 1024 * 1024;

    cudaFuncSetAttribute(attn_kernel, cudaFuncAttributeMaxDynamicSharedMemorySize,
                         AT_SMEM);
    cudaFuncSetAttribute(mma_gemm<false, true>,
                         cudaFuncAttributeMaxDynamicSharedMemorySize, GM_SMEM);
    cudaFuncSetAttribute(mma_gemm<false, false>,
                         cudaFuncAttributeMaxDynamicSharedMemorySize, GM_SMEM);
    cudaFuncSetAttribute(mma_gemm<true, false>,
                         cudaFuncAttributeMaxDynamicSharedMemorySize, GM_SMEM);

    // 1. LayerNorm -> bf16
    ln_kernel<<<4 * 2048, 256>>>(h, gamma, beta);
    // 2. e -> bf16
    cvt_e<<<16384, 256>>>(e);
    // 3. Weight transposes -> bf16
    transpose_w<<<dim3(32, 32), dim3(32, 8)>>>(Wq, wTq);
    transpose_w<<<dim3(32, 32), dim3(32, 8)>>>(Wk, wTk);
    transpose_w<<<dim3(32, 32), dim3(32, 8)>>>(Wv, wTv);
    transpose_w<<<dim3(32, 32), dim3(32, 8)>>>(Wo, wTo);
    // 4-6. Projections (fp16 out)
    mma_gemm<false, true><<<dim3(8, 64),  256, GM_SMEM>>>(
        (const __nv_bfloat16*)p_hsn, wTq, bq, nullptr, p_q);
    mma_gemm<false, true><<<dim3(8, 256), 256, GM_SMEM>>>(
        (const __nv_bfloat16*)p_e, wTk, bk, nullptr, p_k);
    mma_gemm<false, true><<<dim3(8, 256), 256, GM_SMEM>>>(
        (const __nv_bfloat16*)p_e, wTv, bv, nullptr, p_v);
    // 7. Flash attention (fp16 tensor cores)
    attn_kernel<<<dim3(16, 32, 4), 128, AT_SMEM>>>();
    // 8. Output projection + shift + bias + residual
    mma_gemm<true, false><<<dim3(8, 64), 256, GM_SMEM>>>(
        (const __nv_bfloat16*)p_ao, wTo, bo, h, out);
}